// round 17
// baseline (speedup 1.0000x reference)
#include <cuda_runtime.h>
#include <cuda_bf16.h>
#include <math.h>

#define BATCH  512
#define L      100
#define D      128
#define NITEMS 100000
#define NEGV   -1000000000.0f
#define ROWS   (BATCH * L)          // 51200 padded node rows

// ---- scratch blob offsets (floats) ----
#define OFF_HIO   0                         // [ROWS][256]  Hin | Hout
#define OFF_SRZ   (ROWS * 2 * D)            // [ROWS][256]  gi_r+gh_r | gi_z+gh_z
#define OFF_GIN   (OFF_SRZ + ROWS * 2 * D)  // [ROWS][128]
#define OFF_GHN   (OFF_GIN + ROWS * D)      // [ROWS][128]
#define BLOB_SZ   (OFF_GHN + ROWS * D)

__device__ __align__(128) float g_blob[BLOB_SZ];
__device__ int g_cinv[BATCH * L];
__device__ int g_nn[BATCH];
__device__ int g_cntv[BATCH];
__device__ int g_li[BATCH];

// bf16 hi/lo split operands for tensor-core GEMMs
__device__ __align__(16) __nv_bfloat16 g_ehi[NITEMS * D];
__device__ __align__(16) __nv_bfloat16 g_elo[NITEMS * D];
__device__ __align__(16) __nv_bfloat16 g_ahi[BATCH * D];
__device__ __align__(16) __nv_bfloat16 g_alo[BATCH * D];
__device__ __align__(16) __nv_bfloat16 g_hallhi[ROWS * D];
__device__ __align__(16) __nv_bfloat16 g_halllo[ROWS * D];
__device__ __align__(16) __nv_bfloat16 g_xhi[ROWS * D];
__device__ __align__(16) __nv_bfloat16 g_xlo[ROWS * D];
__device__ __align__(16) __nv_bfloat16 g_wiohi[2 * D * D];   // [W_in; W_out]
__device__ __align__(16) __nv_bfloat16 g_wiolo[2 * D * D];
__device__ __align__(16) __nv_bfloat16 g_whhhi[3 * D * D];
__device__ __align__(16) __nv_bfloat16 g_whhlo[3 * D * D];
__device__ __align__(16) __nv_bfloat16 g_wihhi[3 * D * D];
__device__ __align__(16) __nv_bfloat16 g_wihlo[3 * D * D];

// ---- smem / warp-mma / cp.async helpers (arch-generic PTX: sm_80+) ----
__device__ __forceinline__ unsigned smem_u32(const void* p) {
    unsigned a;
    asm("{ .reg .u64 t; cvta.to.shared.u64 t, %1; cvt.u32.u64 %0, t; }" : "=r"(a) : "l"(p));
    return a;
}
__device__ __forceinline__ void sts128(unsigned addr, uint4 v) {
    asm volatile("st.shared.v4.b32 [%0], {%1,%2,%3,%4};"
                 :: "r"(addr), "r"(v.x), "r"(v.y), "r"(v.z), "r"(v.w));
}
__device__ __forceinline__ void ldm4(unsigned& r0, unsigned& r1,
                                     unsigned& r2, unsigned& r3, unsigned addr) {
    asm volatile("ldmatrix.sync.aligned.m8n8.x4.shared.b16 {%0,%1,%2,%3}, [%4];"
                 : "=r"(r0), "=r"(r1), "=r"(r2), "=r"(r3) : "r"(addr));
}
__device__ __forceinline__ void mma16816(float* c, const unsigned* a, const unsigned* b) {
    asm volatile("mma.sync.aligned.m16n8k16.row.col.f32.bf16.bf16.f32 "
                 "{%0,%1,%2,%3}, {%4,%5,%6,%7}, {%8,%9}, {%0,%1,%2,%3};"
                 : "+f"(c[0]), "+f"(c[1]), "+f"(c[2]), "+f"(c[3])
                 : "r"(a[0]), "r"(a[1]), "r"(a[2]), "r"(a[3]),
                   "r"(b[0]), "r"(b[1]));
}
__device__ __forceinline__ void cp16(unsigned dst, const void* src) {
    asm volatile("cp.async.cg.shared.global [%0], [%1], 16;" :: "r"(dst), "l"(src));
}
#define CP_COMMIT()  asm volatile("cp.async.commit_group;" ::: "memory")
#define CP_WAIT(n)   asm volatile("cp.async.wait_group %0;" :: "n"(n) : "memory")

#define TILE 16384
#define PS_SMEM (1024 + 12 * TILE)    // 197,632 B -> 1 CTA/SM

// ---------------------------------------------------------------------------
// staging: one [128][128B] x2 chunk pair, XOR-16B swizzle
// ---------------------------------------------------------------------------
__device__ __forceinline__ void stage_tile(
    unsigned dst0, unsigned dst1, const __nv_bfloat16* gsrc,
    int row0, int maxrow, int tid)
{
    const int r = tid >> 1;            // 0..127
    const int h = tid & 1;
    const int row = row0 + r;
    if (row < maxrow) {
        const uint4* s = (const uint4*)(gsrc + (size_t)row * D);
        #pragma unroll
        for (int jj = 0; jj < 4; jj++) {
            int j = h * 4 + jj;
            unsigned o = r * 128 + ((j ^ (r & 7)) << 4);
            sts128(dst0 + o, s[j]);
            sts128(dst1 + o, s[8 + j]);
        }
    } else {
        uint4 z = make_uint4(0u, 0u, 0u, 0u);
        #pragma unroll
        for (int jj = 0; jj < 4; jj++) {
            int j = h * 4 + jj;
            unsigned o = r * 128 + ((j ^ (r & 7)) << 4);
            sts128(dst0 + o, z);
            sts128(dst1 + o, z);
        }
    }
}

__device__ __forceinline__ void stage_tile_async(
    unsigned dst0, unsigned dst1, const __nv_bfloat16* gsrc,
    int row0, int maxrow, int tid)
{
    const int r = tid >> 1;
    const int h = tid & 1;
    const int row = row0 + r;
    if (row < maxrow) {
        const char* base = (const char*)(gsrc + (size_t)row * D);
        #pragma unroll
        for (int jj = 0; jj < 4; jj++) {
            int j = h * 4 + jj;
            unsigned o = r * 128 + ((j ^ (r & 7)) << 4);
            cp16(dst0 + o, base + j * 16);
            cp16(dst1 + o, base + 128 + j * 16);
        }
    } else {
        uint4 z = make_uint4(0u, 0u, 0u, 0u);
        #pragma unroll
        for (int jj = 0; jj < 4; jj++) {
            int j = h * 4 + jj;
            unsigned o = r * 128 + ((j ^ (r & 7)) << 4);
            sts128(dst0 + o, z);
            sts128(dst1 + o, z);
        }
    }
}

__device__ __forceinline__ unsigned sw_addr(unsigned tile, int row, int kb) {
    return tile + row * 128 + (((unsigned)(kb ^ (row & 7))) << 4);
}

// fused single-pass 3-term: acc += Ahi·Bhi + Alo·Bhi + Ahi·Blo
__device__ __forceinline__ void compute_3term(
    float (&acc)[2][8][4],
    const unsigned* tAhi, const unsigned* tAlo,
    const unsigned* tBhi, const unsigned* tBlo,
    int arow, int asub, int brow0, int bsub)
{
    #pragma unroll
    for (int c = 0; c < 2; c++) {
        #pragma unroll
        for (int kq = 0; kq < 4; kq++) {
            const int kbA = kq * 2 + asub;
            const int kbB = kq * 2 + bsub;
            unsigned bfh[8][2];
            #pragma unroll
            for (int p = 0; p < 4; p++)
                ldm4(bfh[2*p][0], bfh[2*p][1], bfh[2*p+1][0], bfh[2*p+1][1],
                     sw_addr(tBhi[c], brow0 + p * 16, kbB));
            unsigned afh[2][4];
            #pragma unroll
            for (int mf = 0; mf < 2; mf++)
                ldm4(afh[mf][0], afh[mf][1], afh[mf][2], afh[mf][3],
                     sw_addr(tAhi[c], arow + mf * 16, kbA));
            #pragma unroll
            for (int mf = 0; mf < 2; mf++)
                #pragma unroll
                for (int nf = 0; nf < 8; nf++)
                    mma16816(acc[mf][nf], afh[mf], bfh[nf]);
            unsigned afl[2][4];
            #pragma unroll
            for (int mf = 0; mf < 2; mf++)
                ldm4(afl[mf][0], afl[mf][1], afl[mf][2], afl[mf][3],
                     sw_addr(tAlo[c], arow + mf * 16, kbA));
            #pragma unroll
            for (int mf = 0; mf < 2; mf++)
                #pragma unroll
                for (int nf = 0; nf < 8; nf++)
                    mma16816(acc[mf][nf], afl[mf], bfh[nf]);
            unsigned bfl[8][2];
            #pragma unroll
            for (int p = 0; p < 4; p++)
                ldm4(bfl[2*p][0], bfl[2*p][1], bfl[2*p+1][0], bfl[2*p+1][1],
                     sw_addr(tBlo[c], brow0 + p * 16, kbB));
            #pragma unroll
            for (int mf = 0; mf < 2; mf++)
                #pragma unroll
                for (int nf = 0; nf < 8; nf++)
                    mma16816(acc[mf][nf], afh[mf], bfl[nf]);
        }
    }
}

// ---------------------------------------------------------------------------
// K0: ALL fp32 -> bf16 hi/lo splits in one launch
// ---------------------------------------------------------------------------
#define E4   (NITEMS * D / 4)
#define W4   (D * D / 4)
#define W34  (3 * D * D / 4)
#define CONV_GROUPS (E4 + 2 * W4 + 2 * W34)

__global__ __launch_bounds__(256) void conv_all_kernel(
    const float* __restrict__ emb,  const float* __restrict__ W_in,
    const float* __restrict__ W_out, const float* __restrict__ w_hh,
    const float* __restrict__ w_ih)
{
    size_t i = (size_t)blockIdx.x * 256 + threadIdx.x;
    const float* src; __nv_bfloat16 *dhi, *dlo; size_t off;
    if (i < E4)                    { src = emb;   off = i;                 dhi = g_ehi;            dlo = g_elo; }
    else if (i < E4 + W4)          { src = W_in;  off = i - E4;            dhi = g_wiohi;          dlo = g_wiolo; }
    else if (i < E4 + 2 * W4)      { src = W_out; off = i - E4 - W4;       dhi = g_wiohi + D * D;  dlo = g_wiolo + D * D; }
    else if (i < E4 + 2 * W4 + W34){ src = w_hh;  off = i - E4 - 2 * W4;   dhi = g_whhhi;          dlo = g_whhlo; }
    else                           { src = w_ih;  off = i - E4 - 2*W4 - W34; dhi = g_wihhi;        dlo = g_wihlo; }

    float4 v = ((const float4*)src)[off];
    __nv_bfloat162 h01 = __floats2bfloat162_rn(v.x, v.y);
    __nv_bfloat162 h23 = __floats2bfloat162_rn(v.z, v.w);
    __nv_bfloat162 l01 = __floats2bfloat162_rn(v.x - __low2float(h01), v.y - __high2float(h01));
    __nv_bfloat162 l23 = __floats2bfloat162_rn(v.z - __low2float(h23), v.w - __high2float(h23));
    ((__nv_bfloat162*)dhi)[2 * off]     = h01;
    ((__nv_bfloat162*)dhi)[2 * off + 1] = h23;
    ((__nv_bfloat162*)dlo)[2 * off]     = l01;
    ((__nv_bfloat162*)dlo)[2 * off + 1] = l23;
}

// ---------------------------------------------------------------------------
// K1: per-sample graph build + bf16 hi/lo gather
// ---------------------------------------------------------------------------
__global__ __launch_bounds__(256) void build_kernel(const int* __restrict__ x)
{
    __shared__ int s_seq[L], s_rep[L], s_nodes[L], s_cinv[L];
    __shared__ int s_nn, s_cnt;
    const int b = blockIdx.x, tid = threadIdx.x;

    if (tid == 0) { s_nn = 0; s_cnt = 0; }
    if (tid < L) { s_seq[tid] = x[b * L + tid]; s_cinv[tid] = 0; }
    __syncthreads();

    int mypos = 0;
    if (tid < L) {
        int s = s_seq[tid];
        int rep = (s != 0);
        for (int j = 0; j < tid; j++) {
            int sj = s_seq[j];
            if (sj != 0) { mypos++; if (sj == s) rep = 0; }
        }
        s_rep[tid] = rep;
    }
    __syncthreads();

    if (tid < L) {
        int s = s_seq[tid];
        if (s != 0) {
            int rank = 0;
            for (int j = 0; j < L; j++)
                if (s_rep[j] && s_seq[j] < s) rank++;
            if (s_rep[tid]) { s_nodes[rank] = s; atomicAdd(&s_nn, 1); }
            s_cinv[mypos] = rank;
            atomicAdd(&s_cnt, 1);
        }
    }
    __syncthreads();

    const int nn = s_nn, cnt = s_cnt;

    for (int idx = tid; idx < L * 16; idx += 256) {
        int r = idx >> 4, q = idx & 15;
        uint4 vh = make_uint4(0u, 0u, 0u, 0u), vl = vh;
        if (r < nn) {
            vh = ((const uint4*)(g_ehi + (size_t)s_nodes[r] * D))[q];
            vl = ((const uint4*)(g_elo + (size_t)s_nodes[r] * D))[q];
        }
        ((uint4*)(g_hallhi + ((size_t)b * L + r) * D))[q] = vh;
        ((uint4*)(g_halllo + ((size_t)b * L + r) * D))[q] = vl;
    }
    if (tid < L) g_cinv[b * L + tid] = s_cinv[tid];
    if (tid == 0) {
        g_nn[b] = nn;
        g_cntv[b] = cnt;
        g_li[b] = (cnt > 0) ? s_cinv[cnt - 1] : 0;
    }
}

// ---------------------------------------------------------------------------
// Persistent internal GEMM: weights resident, A streamed (double-buffered
// cp.async for NPAIR=1; sequential pair staging for NPAIR=2).
// C(m-tile, n0) = sum_pairs 3-term(A_pair, B_pair)
// ---------------------------------------------------------------------------
template<int NPAIR>
__global__ void __launch_bounds__(256) internal_persist_kernel(
    const __nv_bfloat16* __restrict__ A0hi, const __nv_bfloat16* __restrict__ A0lo,
    const __nv_bfloat16* __restrict__ B0hi, const __nv_bfloat16* __restrict__ B0lo,
    const __nv_bfloat16* __restrict__ A1hi, const __nv_bfloat16* __restrict__ A1lo,
    const __nv_bfloat16* __restrict__ B1hi, const __nv_bfloat16* __restrict__ B1lo,
    int coff, int ldc, int mtiles)
{
    extern __shared__ char dsm[];
    const int tid = threadIdx.x, wid = tid >> 5, lane = tid & 31;
    const int n0 = blockIdx.y * 128;
    unsigned tb = (smem_u32(dsm) + 1023) & ~1023u;

    unsigned b0hi[2] = { tb,            tb + TILE };
    unsigned b0lo[2] = { tb + 2*TILE,   tb + 3*TILE };
    unsigned b1hi[2] = { tb + 4*TILE,   tb + 5*TILE };
    unsigned b1lo[2] = { tb + 6*TILE,   tb + 7*TILE };

    // resident weights
    stage_tile(b0hi[0], b0hi[1], B0hi, n0, 0x7fffffff, tid);
    stage_tile(b0lo[0], b0lo[1], B0lo, n0, 0x7fffffff, tid);
    if (NPAIR == 2) {
        stage_tile(b1hi[0], b1hi[1], B1hi, n0, 0x7fffffff, tid);
        stage_tile(b1lo[0], b1lo[1], B1lo, n0, 0x7fffffff, tid);
    }

    const int m0w = (wid & 3) * 32;
    const int n0w = (wid >> 2) * 64;
    const int arow = m0w + (lane & 15);
    const int asub = lane >> 4;
    const int brow0 = n0w + ((lane >> 4) << 3) + (lane & 7);
    const int bsub  = (lane >> 3) & 1;
    const int rbase = lane >> 2;
    const int cbase = (lane & 3) * 2;
    float* C = g_blob + coff;

    if (NPAIR == 1) {
        // A double-buffered: buf b at tb + (4 + 4b)*TILE
        unsigned ab[2][4];
        #pragma unroll
        for (int b = 0; b < 2; b++)
            #pragma unroll
            for (int t = 0; t < 4; t++)
                ab[b][t] = tb + (4 + 4 * b + t) * TILE;   // hi0,hi1,lo0,lo1

        int buf = 0;
        int mt = blockIdx.x;
        if (mt < mtiles) {
            stage_tile_async(ab[0][0], ab[0][1], A0hi, mt * 128, 0x7fffffff, tid);
            stage_tile_async(ab[0][2], ab[0][3], A0lo, mt * 128, 0x7fffffff, tid);
            CP_COMMIT();
        }
        for (; mt < mtiles; mt += gridDim.x) {
            int mtn = mt + gridDim.x;
            bool pf = mtn < mtiles;
            if (pf) {
                stage_tile_async(ab[buf^1][0], ab[buf^1][1], A0hi, mtn * 128, 0x7fffffff, tid);
                stage_tile_async(ab[buf^1][2], ab[buf^1][3], A0lo, mtn * 128, 0x7fffffff, tid);
                CP_COMMIT();
            }
            if (pf) { CP_WAIT(1); } else { CP_WAIT(0); }
            __syncthreads();

            float acc[2][8][4];
            #pragma unroll
            for (int i = 0; i < 2; i++)
                #pragma unroll
                for (int j = 0; j < 8; j++)
                    #pragma unroll
                    for (int q = 0; q < 4; q++) acc[i][j][q] = 0.f;

            unsigned ahi[2] = { ab[buf][0], ab[buf][1] };
            unsigned alo[2] = { ab[buf][2], ab[buf][3] };
            compute_3term(acc, ahi, alo, b0hi, b0lo, arow, asub, brow0, bsub);

            const int m0 = mt * 128;
            #pragma unroll
            for (int mf = 0; mf < 2; mf++) {
                const int mA = m0 + m0w + mf * 16 + rbase;
                #pragma unroll
                for (int nf = 0; nf < 8; nf++) {
                    const int n = n0 + n0w + nf * 8 + cbase;
                    float2 vA = { acc[mf][nf][0], acc[mf][nf][1] };
                    float2 vB = { acc[mf][nf][2], acc[mf][nf][3] };
                    *(float2*)&C[(size_t)mA * ldc + n] = vA;
                    *(float2*)&C[(size_t)(mA + 8) * ldc + n] = vB;
                }
            }
            __syncthreads();
            buf ^= 1;
        }
    } else {
        // NPAIR == 2: single A buffer at tb + 8*TILE, sequential pairs
        unsigned as_[4] = { tb + 8*TILE, tb + 9*TILE, tb + 10*TILE, tb + 11*TILE };
        unsigned ahi[2] = { as_[0], as_[1] };
        unsigned alo[2] = { as_[2], as_[3] };
        __syncthreads();   // resident B visible

        for (int mt = blockIdx.x; mt < mtiles; mt += gridDim.x) {
            stage_tile_async(as_[0], as_[1], A0hi, mt * 128, 0x7fffffff, tid);
            stage_tile_async(as_[2], as_[3], A0lo, mt * 128, 0x7fffffff, tid);
            CP_COMMIT(); CP_WAIT(0);
            __syncthreads();

            float acc[2][8][4];
            #pragma unroll
            for (int i = 0; i < 2; i++)
                #pragma unroll
                for (int j = 0; j < 8; j++)
                    #pragma unroll
                    for (int q = 0; q < 4; q++) acc[i][j][q] = 0.f;

            compute_3term(acc, ahi, alo, b0hi, b0lo, arow, asub, brow0, bsub);
            __syncthreads();

            stage_tile_async(as_[0], as_[1], A1hi, mt * 128, 0x7fffffff, tid);
            stage_tile_async(as_[2], as_[3], A1lo, mt * 128, 0x7fffffff, tid);
            CP_COMMIT(); CP_WAIT(0);
            __syncthreads();

            compute_3term(acc, ahi, alo, b1hi, b1lo, arow, asub, brow0, bsub);

            const int m0 = mt * 128;
            #pragma unroll
            for (int mf = 0; mf < 2; mf++) {
                const int mA = m0 + m0w + mf * 16 + rbase;
                #pragma unroll
                for (int nf = 0; nf < 8; nf++) {
                    const int n = n0 + n0w + nf * 8 + cbase;
                    float2 vA = { acc[mf][nf][0], acc[mf][nf][1] };
                    float2 vB = { acc[mf][nf][2], acc[mf][nf][3] };
                    *(float2*)&C[(size_t)mA * ldc + n] = vA;
                    *(float2*)&C[(size_t)(mA + 8) * ldc + n] = vB;
                }
            }
            __syncthreads();
        }
    }
}

// ---------------------------------------------------------------------------
// Persistent score GEMM: A (h_read) resident, emb tiles streamed with
// double-buffered cp.async; epilogue with cnt>=2 masking.
// ---------------------------------------------------------------------------
__global__ void __launch_bounds__(256) score_persist_kernel(
    const __nv_bfloat16* __restrict__ Ahi, const __nv_bfloat16* __restrict__ Alo,
    const __nv_bfloat16* __restrict__ Bhi, const __nv_bfloat16* __restrict__ Blo,
    float* __restrict__ out)
{
    extern __shared__ char dsm[];
    const int tid = threadIdx.x, wid = tid >> 5, lane = tid & 31;
    const int m0 = blockIdx.x * 128;
    unsigned tb = (smem_u32(dsm) + 1023) & ~1023u;

    unsigned tahi[2] = { tb,          tb + TILE };
    unsigned talo[2] = { tb + 2*TILE, tb + 3*TILE };
    unsigned bb[2][4];
    #pragma unroll
    for (int b = 0; b < 2; b++)
        #pragma unroll
        for (int t = 0; t < 4; t++)
            bb[b][t] = tb + (4 + 4 * b + t) * TILE;     // hi0,hi1,lo0,lo1

    stage_tile(tahi[0], tahi[1], Ahi, m0, BATCH, tid);
    stage_tile(talo[0], talo[1], Alo, m0, BATCH, tid);

    const int m0w = (wid & 3) * 32;
    const int n0w = (wid >> 2) * 64;
    const int arow = m0w + (lane & 15);
    const int asub = lane >> 4;
    const int brow0 = n0w + ((lane >> 4) << 3) + (lane & 7);
    const int bsub  = (lane >> 3) & 1;
    const int rbase = lane >> 2;
    const int cbase = (lane & 3) * 2;

    // per-CTA-invariant mask bits (hoisted out of the n loop)
    const int mA0 = m0 + m0w + rbase;
    const bool ok[4] = { g_cntv[mA0] >= 2,      g_cntv[mA0 + 8] >= 2,
                         g_cntv[mA0 + 16] >= 2, g_cntv[mA0 + 24] >= 2 };

    const int NT = (NITEMS + 127) / 128;     // 782
    int buf = 0;
    int nt = blockIdx.y;
    if (nt < NT) {
        stage_tile_async(bb[0][0], bb[0][1], Bhi, nt * 128, NITEMS, tid);
        stage_tile_async(bb[0][2], bb[0][3], Blo, nt * 128, NITEMS, tid);
        CP_COMMIT();
    }
    for (; nt < NT; nt += gridDim.y) {
        int ntn = nt + gridDim.y;
        bool pf = ntn < NT;
        if (pf) {
            stage_tile_async(bb[buf^1][0], bb[buf^1][1], Bhi, ntn * 128, NITEMS, tid);
            stage_tile_async(bb[buf^1][2], bb[buf^1][3], Blo, ntn * 128, NITEMS, tid);
            CP_COMMIT();
        }
        if (pf) { CP_WAIT(1); } else { CP_WAIT(0); }
        __syncthreads();

        float acc[2][8][4];
        #pragma unroll
        for (int i = 0; i < 2; i++)
            #pragma unroll
            for (int j = 0; j < 8; j++)
                #pragma unroll
                for (int q = 0; q < 4; q++) acc[i][j][q] = 0.f;

        unsigned bhi[2] = { bb[buf][0], bb[buf][1] };
        unsigned blo[2] = { bb[buf][2], bb[buf][3] };
        compute_3term(acc, tahi, talo, bhi, blo, arow, asub, brow0, bsub);

        const int n0 = nt * 128;
        #pragma unroll
        for (int mf = 0; mf < 2; mf++) {
            const int mA = mA0 + mf * 16;
            const bool okA = ok[mf * 2], okB = ok[mf * 2 + 1];
            #pragma unroll
            for (int nf = 0; nf < 8; nf++) {
                const int n = n0 + n0w + nf * 8 + cbase;
                if (n < NITEMS) {
                    float2 vA, vB;
                    if (okA) { vA.x = acc[mf][nf][0]; vA.y = acc[mf][nf][1]; }
                    else     { vA.x = (n == 0) ? 0.0f : NEGV; vA.y = NEGV; }
                    if (okB) { vB.x = acc[mf][nf][2]; vB.y = acc[mf][nf][3]; }
                    else     { vB.x = (n == 0) ? 0.0f : NEGV; vB.y = NEGV; }
                    *(float2*)&out[(size_t)mA * NITEMS + n] = vA;
                    *(float2*)&out[(size_t)(mA + 8) * NITEMS + n] = vB;
                }
            }
        }
        __syncthreads();
        buf ^= 1;
    }
}

// ---------------------------------------------------------------------------
// K3: per-sample edge aggregation.  X = Hin + agg(Hout[src])/deg -> bf16 hi/lo
// ---------------------------------------------------------------------------
__global__ __launch_bounds__(256) void agg_kernel()
{
    extern __shared__ float agg[];            // L*D floats
    __shared__ int   cinv[L];
    __shared__ float rdeg[L];
    const int b = blockIdx.x, tid = threadIdx.x;

    if (tid < L) { cinv[tid] = g_cinv[b * L + tid]; rdeg[tid] = 0.f; }
    for (int i = tid; i < L * D / 4; i += 256)
        ((float4*)agg)[i] = make_float4(0.f, 0.f, 0.f, 0.f);
    __syncthreads();

    const int cnt = g_cntv[b];
    if (tid < cnt - 1) atomicAdd(&rdeg[cinv[tid + 1]], 1.0f);
    __syncthreads();
    if (tid < L) rdeg[tid] = 1.0f / fmaxf(rdeg[tid], 1.0f);

    const float* Hio = g_blob + OFF_HIO + (size_t)b * L * 2 * D;
    const int nedge = (cnt >= 1) ? cnt - 1 : 0;
    for (int idx = tid; idx < nedge * D; idx += 256) {
        int t = idx >> 7, k = idx & 127;
        atomicAdd(&agg[cinv[t + 1] * D + k], Hio[(size_t)cinv[t] * 2 * D + D + k]);
    }
    __syncthreads();

    for (int idx = tid; idx < L * D; idx += 256) {
        int r = idx >> 7;
        float v = Hio[(size_t)r * 2 * D + (idx & 127)] + agg[idx] * rdeg[r];
        __nv_bfloat16 h = __float2bfloat16(v);
        g_xhi[(size_t)b * L * D + idx] = h;
        g_xlo[(size_t)b * L * D + idx] = __float2bfloat16(v - __bfloat162float(h));
    }
}

// ---------------------------------------------------------------------------
// K4: fused GRU + attention readout (one CTA per sample, H in SMEM)
// ---------------------------------------------------------------------------
__global__ __launch_bounds__(256) void gru_attn_kernel(
    const float* __restrict__ b_ih, const float* __restrict__ b_hh,
    const float* __restrict__ W_read, const float* __restrict__ b_read)
{
    extern __shared__ float H[];              // L*D floats
    __shared__ float hlast[D], loc[D], sc[L];
    const int b = blockIdx.x, tid = threadIdx.x;
    const int nn = g_nn[b], li = g_li[b];

    for (int idx = tid; idx < L * D; idx += 256) {
        int row = idx >> 7, j = idx & 127;
        size_t base = (size_t)b * L + row;
        float sr  = g_blob[OFF_SRZ + base * 256 + j];
        float sz  = g_blob[OFF_SRZ + base * 256 + 128 + j];
        float gin = g_blob[OFF_GIN + base * 128 + j];
        float ghn = g_blob[OFF_GHN + base * 128 + j];
        float h0  = __bfloat162float(g_hallhi[base * 128 + j])
                  + __bfloat162float(g_halllo[base * 128 + j]);
        float r = 1.0f / (1.0f + expf(-(sr + b_ih[j] + b_hh[j])));
        float z = 1.0f / (1.0f + expf(-(sz + b_ih[D + j] + b_hh[D + j])));
        float n = tanhf(gin + b_ih[2 * D + j] + r * (ghn + b_hh[2 * D + j]));
        H[idx] = (1.0f - z) * n + z * h0;
    }
    __syncthreads();

    if (tid < D) hlast[tid] = H[li * D + tid];
    __syncthreads();

    const int w = tid >> 5, lane = tid & 31;
    for (int r = w; r < nn; r += 8) {
        const float* hr = H + r * D;
        float acc = 0.f;
        #pragma unroll
        for (int k = lane; k < D; k += 32) acc = fmaf(hr[k], hlast[k], acc);
        #pragma unroll
        for (int off = 16; off; off >>= 1)
            acc += __shfl_down_sync(0xffffffffu, acc, off);
        if (lane == 0) sc[r] = acc;
    }
    __syncthreads();

    if (tid == 0) {
        float m = -1e30f;
        for (int i = 0; i < nn; i++) m = fmaxf(m, sc[i]);
        float s = 0.f;
        for (int i = 0; i < nn; i++) { float e = expf(sc[i] - m); sc[i] = e; s += e; }
        float inv = (s > 0.f) ? 1.0f / s : 0.f;
        for (int i = 0; i < nn; i++) sc[i] *= inv;
    }
    __syncthreads();

    if (tid < D) {
        float acc = 0.f;
        for (int r = 0; r < nn; r++) acc = fmaf(sc[r], H[r * D + tid], acc);
        loc[tid] = acc;
    }
    __syncthreads();

    #pragma unroll
    for (int t = 0; t < 16; t++) {
        int j = w * 16 + t;
        const float* wr = W_read + (size_t)j * (3 * D);
        float acc = 0.f;
        #pragma unroll
        for (int k = lane; k < D; k += 32)
            acc += wr[k] * hlast[k] + wr[D + k] * loc[k];
        #pragma unroll
        for (int off = 16; off; off >>= 1)
            acc += __shfl_down_sync(0xffffffffu, acc, off);
        if (lane == 0) {
            float hv = tanhf(acc + b_read[j]);
            __nv_bfloat16 h = __float2bfloat16(hv);
            g_ahi[b * D + j] = h;
            g_alo[b * D + j] = __float2bfloat16(hv - __bfloat162float(h));
        }
    }
}

// ---------------------------------------------------------------------------
extern "C" void kernel_launch(void* const* d_in, const int* in_sizes, int n_in,
                              void* d_out, int out_size)
{
    const int*   x      = (const int*)  d_in[0];
    // d_in[1] = attn_mask (unused by reference)
    const float* emb    = (const float*)d_in[2];
    const float* W_in   = (const float*)d_in[3];
    const float* W_out  = (const float*)d_in[4];
    const float* w_ih   = (const float*)d_in[5];
    const float* w_hh   = (const float*)d_in[6];
    const float* b_ih   = (const float*)d_in[7];
    const float* b_hh   = (const float*)d_in[8];
    const float* W_read = (const float*)d_in[9];
    const float* b_read = (const float*)d_in[10];
    float* out = (float*)d_out;

    cudaFuncSetAttribute(agg_kernel,
        cudaFuncAttributeMaxDynamicSharedMemorySize, L * D * (int)sizeof(float));
    cudaFuncSetAttribute(gru_attn_kernel,
        cudaFuncAttributeMaxDynamicSharedMemorySize, L * D * (int)sizeof(float));
    cudaFuncSetAttribute(internal_persist_kernel<1>,
        cudaFuncAttributeMaxDynamicSharedMemorySize, PS_SMEM);
    cudaFuncSetAttribute(internal_persist_kernel<2>,
        cudaFuncAttributeMaxDynamicSharedMemorySize, PS_SMEM);
    cudaFuncSetAttribute(score_persist_kernel,
        cudaFuncAttributeMaxDynamicSharedMemorySize, PS_SMEM);

    __nv_bfloat16 *ehi, *elo, *ahi, *alo, *hallhi, *halllo, *xhi, *xlo;
    __nv_bfloat16 *wiohi, *wiolo, *whhhi, *whhlo, *wihhi, *wihlo;
    cudaGetSymbolAddress((void**)&ehi,    g_ehi);
    cudaGetSymbolAddress((void**)&elo,    g_elo);
    cudaGetSymbolAddress((void**)&ahi,    g_ahi);
    cudaGetSymbolAddress((void**)&alo,    g_alo);
    cudaGetSymbolAddress((void**)&hallhi, g_hallhi);
    cudaGetSymbolAddress((void**)&halllo, g_halllo);
    cudaGetSymbolAddress((void**)&xhi,    g_xhi);
    cudaGetSymbolAddress((void**)&xlo,    g_xlo);
    cudaGetSymbolAddress((void**)&wiohi,  g_wiohi);
    cudaGetSymbolAddress((void**)&wiolo,  g_wiolo);
    cudaGetSymbolAddress((void**)&whhhi,  g_whhhi);
    cudaGetSymbolAddress((void**)&whhlo,  g_whhlo);
    cudaGetSymbolAddress((void**)&wihhi,  g_wihhi);
    cudaGetSymbolAddress((void**)&wihlo,  g_wihlo);

    // K0: all fp32 -> bf16 hi/lo conversions in one launch
    conv_all_kernel<<<CONV_GROUPS / 256, 256>>>(emb, W_in, W_out, w_hh, w_ih);

    // K1: graph build + bf16 hi/lo gather
    build_kernel<<<BATCH, 256>>>(x);

    // G1: Hin | Hout = Hall @ [W_in; W_out]^T  (persistent, weights resident)
    internal_persist_kernel<1><<<dim3(74, 2), 256, PS_SMEM>>>(
        hallhi, halllo, wiohi, wiolo,
        nullptr, nullptr, nullptr, nullptr, OFF_HIO, 2 * D, ROWS / 128);

    // G_ghn: gh_n = Hall @ w_hh_n^T
    internal_persist_kernel<1><<<dim3(148, 1), 256, PS_SMEM>>>(
        hallhi, halllo, whhhi + 2 * D * D, whhlo + 2 * D * D,
        nullptr, nullptr, nullptr, nullptr, OFF_GHN, D, ROWS / 128);

    // K3: X = Hin + agg/deg -> bf16 hi/lo
    agg_kernel<<<BATCH, 256, L * D * sizeof(float)>>>();

    // G_rz: s_rz = X @ w_ih_rz^T + Hall @ w_hh_rz^T   (dual-pair, B resident)
    internal_persist_kernel<2><<<dim3(74, 2), 256, PS_SMEM>>>(
        xhi, xlo, wihhi, wihlo,
        hallhi, halllo, whhhi, whhlo, OFF_SRZ, 2 * D, ROWS / 128);

    // G_gin: gi_n = X @ w_ih_n^T
    internal_persist_kernel<1><<<dim3(148, 1), 256, PS_SMEM>>>(
        xhi, xlo, wihhi + 2 * D * D, wihlo + 2 * D * D,
        nullptr, nullptr, nullptr, nullptr, OFF_GIN, D, ROWS / 128);

    // K4: fused GRU + attention -> h_read hi/lo
    gru_attn_kernel<<<BATCH, 256, L * D * sizeof(float)>>>(b_ih, b_hh, W_read, b_read);

    // K6: persistent tensor-core score GEMM (A resident, emb streamed)
    score_persist_kernel<<<dim3(BATCH / 128, 37), 256, PS_SMEM>>>(
        ahi, alo, ehi, elo, out);
}